// round 5
// baseline (speedup 1.0000x reference)
#include <cuda_runtime.h>

#define H      4096
#define TMAX   16384
#define EXP    8
#define FULLM  0xFFFFFFFFu
#define STAGES 6
#define ROWB   16384            // bytes per row stage (1024 threads * 16B = full row)

// Phase-1 partials: [row][32 warps][8 experts] = 16 MB
__device__ float g_scratch[(size_t)TMAX * 32 * EXP];

typedef unsigned long long u64;

__device__ __forceinline__ u64 fma2(u64 a, u64 b, u64 c) {
    u64 d; asm("fma.rn.f32x2 %0,%1,%2,%3;" : "=l"(d) : "l"(a), "l"(b), "l"(c)); return d;
}
__device__ __forceinline__ u64 mul2(u64 a, u64 b) {
    u64 d; asm("mul.rn.f32x2 %0,%1,%2;" : "=l"(d) : "l"(a), "l"(b)); return d;
}
__device__ __forceinline__ u64 add2(u64 a, u64 b) {
    u64 d; asm("add.rn.f32x2 %0,%1,%2;" : "=l"(d) : "l"(a), "l"(b)); return d;
}
__device__ __forceinline__ float hadd2(u64 v) {
    float lo = __uint_as_float((unsigned)v);
    float hi = __uint_as_float((unsigned)(v >> 32));
    return lo + hi;
}
__device__ __forceinline__ void lds128(u64& a, u64& b, unsigned addr) {
    asm volatile("ld.shared.v2.u64 {%0,%1},[%2];" : "=l"(a), "=l"(b) : "r"(addr));
}
__device__ __forceinline__ void cp16(unsigned saddr, const void* gaddr) {
    asm volatile("cp.async.cg.shared.global [%0], [%1], 16;" :: "r"(saddr), "l"(gaddr));
}
__device__ __forceinline__ void cp_commit() {
    asm volatile("cp.async.commit_group;" ::: "memory");
}
__device__ __forceinline__ void cp_wait5() {
    asm volatile("cp.async.wait_group 5;" ::: "memory");
}

// Reduce 8 per-lane values across 32 lanes (butterfly, used by phase 2).
// Result: lane 4e holds the sum for expert e.
__device__ __forceinline__ float reduce8(float a[8]) {
    const int lane = threadIdx.x & 31;
    {
        bool hi = (lane & 16) != 0;
        float s0 = hi ? a[0] : a[4];
        float s1 = hi ? a[1] : a[5];
        float s2 = hi ? a[2] : a[6];
        float s3 = hi ? a[3] : a[7];
        s0 = __shfl_xor_sync(FULLM, s0, 16);
        s1 = __shfl_xor_sync(FULLM, s1, 16);
        s2 = __shfl_xor_sync(FULLM, s2, 16);
        s3 = __shfl_xor_sync(FULLM, s3, 16);
        a[0] = (hi ? a[4] : a[0]) + s0;
        a[1] = (hi ? a[5] : a[1]) + s1;
        a[2] = (hi ? a[6] : a[2]) + s2;
        a[3] = (hi ? a[7] : a[3]) + s3;
    }
    {
        bool hi = (lane & 8) != 0;
        float s0 = hi ? a[0] : a[2];
        float s1 = hi ? a[1] : a[3];
        s0 = __shfl_xor_sync(FULLM, s0, 8);
        s1 = __shfl_xor_sync(FULLM, s1, 8);
        a[0] = (hi ? a[2] : a[0]) + s0;
        a[1] = (hi ? a[3] : a[1]) + s1;
    }
    {
        bool hi = (lane & 4) != 0;
        float s0 = hi ? a[0] : a[1];
        s0 = __shfl_xor_sync(FULLM, s0, 4);
        a[0] = (hi ? a[1] : a[0]) + s0;
    }
    float v = a[0];
    v += __shfl_xor_sync(FULLM, v, 2);
    v += __shfl_xor_sync(FULLM, v, 1);
    return v;
}

// ── Phase 1: streaming GEMV partials.
//   1024 threads. Warp w owns chunk of 128 floats (512B). Lane l = (expert
//   l&7, k-quarter g=l>>3). x staged by per-lane cp.async into the warp's
//   chunk; lanes read LDS.128 at slot 4j+g (conflict-free broadcast,
//   immediate offsets). Cross-lane reduce = 2 shfls. No block sync.
__global__ void __launch_bounds__(1024, 1)
router_p1(const float* __restrict__ x, const float* __restrict__ W, int T) {
    extern __shared__ char smem[];   // STAGES * 16KB = 96KB

    const int tid  = threadIdx.x;
    const int lane = tid & 31;
    const int warp = tid >> 5;
    const int g    = lane >> 3;
    const int e    = lane & 7;
    const int nb   = gridDim.x;

    // W regs: lane's expert e, float4 at slot (4j+g) of this warp's 128-chunk
    u64 wlo[8], whi[8];
#pragma unroll
    for (int j = 0; j < 8; j++) {
        ulonglong2 t = *reinterpret_cast<const ulonglong2*>(
            W + e * H + warp * 128 + (4 * j + g) * 4);
        wlo[j] = t.x; whi[j] = t.y;
    }

    unsigned sbase;
    asm("{ .reg .u64 t; cvta.to.shared.u64 t, %1; cvt.u32.u64 %0, t; }"
        : "=r"(sbase) : "l"(smem));
    const unsigned cpDst0 = sbase + warp * 512 + lane * 16;
    const unsigned ldB0   = sbase + warp * 512 + g * 16;

    const char* xg = reinterpret_cast<const char*>(x);
    const size_t myOff = (size_t)warp * 512 + lane * 16;

    const int r0 = blockIdx.x;

    // prologue: fill STAGES groups
#pragma unroll
    for (int s = 0; s < STAGES; s++) {
        int r = r0 + s * nb;
        if (r < T) cp16(cpDst0 + s * ROWB, xg + (size_t)r * ROWB + myOff);
        cp_commit();
    }

    int s = 0;
    for (int r = r0; r < T; r += nb) {
        cp_wait5();
        __syncwarp();

        const unsigned B = ldB0 + s * ROWB;
        u64 xlo, xhi;
        lds128(xlo, xhi, B);
        u64 acc0 = mul2(xlo, wlo[0]);
        u64 acc1 = mul2(xhi, whi[0]);
#pragma unroll
        for (int j = 1; j < 8; j++) {
            lds128(xlo, xhi, B + j * 64);
            acc0 = fma2(xlo, wlo[j], acc0);
            acc1 = fma2(xhi, whi[j], acc1);
        }
        float v = hadd2(add2(acc0, acc1));
        v += __shfl_xor_sync(FULLM, v, 8);
        v += __shfl_xor_sync(FULLM, v, 16);
        if (lane < 8)
            g_scratch[((size_t)r * 32 + warp) * EXP + lane] = v;

        int rp = r + STAGES * nb;
        if (rp < T) cp16(cpDst0 + s * ROWB, xg + (size_t)rp * ROWB + myOff);
        cp_commit();

        s = (s == STAGES - 1) ? 0 : s + 1;
    }
}

// ── Phase 2: one warp per row. Lane l loads slot l (8 floats). Butterfly
//   reduce + shfl softmax; top-2 via 8-way broadcast + flat register scan.
__global__ void __launch_bounds__(256)
router_p2(int T, float* __restrict__ out, int flags) {
    const int lane = threadIdx.x & 31;
    const int r    = (blockIdx.x * 256 + threadIdx.x) >> 5;
    if (r >= T) return;

    const float4* p = reinterpret_cast<const float4*>(g_scratch + ((size_t)r * 32 + lane) * EXP);
    float4 u = p[0], v = p[1];

    float a[EXP] = {u.x, u.y, u.z, u.w, v.x, v.y, v.z, v.w};
    float t = reduce8(a);  // lane 4e -> logit[e]

    // softmax over the 8 distributed logits (orbit of lane bits {16,8,4})
    float m = t;
    m = fmaxf(m, __shfl_xor_sync(FULLM, m, 16));
    m = fmaxf(m, __shfl_xor_sync(FULLM, m, 8));
    m = fmaxf(m, __shfl_xor_sync(FULLM, m, 4));
    float pz = __expf(t - m);
    float sden = pz;
    sden += __shfl_xor_sync(FULLM, sden, 16);
    sden += __shfl_xor_sync(FULLM, sden, 8);
    sden += __shfl_xor_sync(FULLM, sden, 4);
    float sc = __fdividef(pz, sden);

    int e = ((lane >> 4) & 1) * 4 + ((lane >> 3) & 1) * 2 + ((lane >> 2) & 1);
    if ((lane & 3) == 0)
        out[(size_t)r * EXP + e] = sc;

    // broadcast all 8 scores, then flat per-lane top-2 (ties -> lower index)
    float se[EXP];
#pragma unroll
    for (int j = 0; j < EXP; j++) {
        int src = ((j & 4) << 2) | ((j & 2) << 2) | ((j & 1) << 2);  // lane 4e for e=j
        se[j] = __shfl_sync(FULLM, sc, src);
    }
    float v1 = se[0]; int i1 = 0;
#pragma unroll
    for (int j = 1; j < EXP; j++)
        if (se[j] > v1) { v1 = se[j]; i1 = j; }
    float v2 = -1.0f; int i2 = 0;
#pragma unroll
    for (int j = 0; j < EXP; j++)
        if (j != i1 && se[j] > v2) { v2 = se[j]; i2 = j; }

    if (lane == 0) {
        float* outW = out + (size_t)T * EXP;
        float* outI = out + (size_t)T * (EXP + 2);
        if (flags & 1) {
            outW[(size_t)r * 2 + 0] = v1;
            outW[(size_t)r * 2 + 1] = v2;
        }
        if (flags & 2) {
            outI[(size_t)r * 2 + 0] = (float)i1;
            outI[(size_t)r * 2 + 1] = (float)i2;
        }
    }
}

extern "C" void kernel_launch(void* const* d_in, const int* in_sizes, int n_in,
                              void* d_out, int out_size) {
    const float* x = (const float*)d_in[0];
    const float* W = (const float*)d_in[1];

    int T = in_sizes[0] / H;  // 16384

    int dev = 0;
    cudaGetDevice(&dev);
    int sm = 148;
    cudaDeviceGetAttribute(&sm, cudaDevAttrMultiProcessorCount, dev);

    int flags = 0;
    if (out_size >= T * (EXP + 2)) flags |= 1;
    if (out_size >= T * (EXP + 4)) flags |= 2;

    static int smemSet = 0;
    if (!smemSet) {
        cudaFuncSetAttribute(router_p1, cudaFuncAttributeMaxDynamicSharedMemorySize,
                             STAGES * ROWB);
        smemSet = 1;
    }

    router_p1<<<sm, 1024, STAGES * ROWB>>>(x, W, T);
    int blocks2 = (T * 32 + 255) / 256;   // one warp per row
    router_p2<<<blocks2, 256>>>(T, (float*)d_out, flags);
}

// round 6
// speedup vs baseline: 1.1774x; 1.1774x over previous
#include <cuda_runtime.h>

#define H      4096
#define TMAX   16384
#define EXP    8
#define FULLM  0xFFFFFFFFu
#define STAGES 8
#define ROWB   16384            // bytes per row stage (full 4096-float row)

// Phase-1 partials: [row][16 warps][8 experts] = 8 MB
__device__ float g_scratch[(size_t)TMAX * 16 * EXP];

typedef unsigned long long u64;

__device__ __forceinline__ u64 fma2(u64 a, u64 b, u64 c) {
    u64 d; asm("fma.rn.f32x2 %0,%1,%2,%3;" : "=l"(d) : "l"(a), "l"(b), "l"(c)); return d;
}
__device__ __forceinline__ u64 mul2(u64 a, u64 b) {
    u64 d; asm("mul.rn.f32x2 %0,%1,%2;" : "=l"(d) : "l"(a), "l"(b)); return d;
}
__device__ __forceinline__ float hadd2(u64 v) {
    float lo = __uint_as_float((unsigned)v);
    float hi = __uint_as_float((unsigned)(v >> 32));
    return lo + hi;
}
__device__ __forceinline__ void lds128(u64& a, u64& b, unsigned addr) {
    asm volatile("ld.shared.v2.u64 {%0,%1},[%2];" : "=l"(a), "=l"(b) : "r"(addr));
}
__device__ __forceinline__ void cp16(unsigned saddr, const void* gaddr) {
    asm volatile("cp.async.cg.shared.global [%0], [%1], 16;" :: "r"(saddr), "l"(gaddr));
}
__device__ __forceinline__ void cp_commit() {
    asm volatile("cp.async.commit_group;" ::: "memory");
}
__device__ __forceinline__ void cp_waitN() {
    asm volatile("cp.async.wait_group %0;" :: "n"(STAGES - 1) : "memory");
}

// Reduce 8 per-lane values across 32 lanes (vector-halving butterfly, 9 shfls).
// Result: lane 4e holds the sum for expert e.
__device__ __forceinline__ float reduce8(float a[8]) {
    const int lane = threadIdx.x & 31;
    {
        bool hi = (lane & 16) != 0;
        float s0 = hi ? a[0] : a[4];
        float s1 = hi ? a[1] : a[5];
        float s2 = hi ? a[2] : a[6];
        float s3 = hi ? a[3] : a[7];
        s0 = __shfl_xor_sync(FULLM, s0, 16);
        s1 = __shfl_xor_sync(FULLM, s1, 16);
        s2 = __shfl_xor_sync(FULLM, s2, 16);
        s3 = __shfl_xor_sync(FULLM, s3, 16);
        a[0] = (hi ? a[4] : a[0]) + s0;
        a[1] = (hi ? a[5] : a[1]) + s1;
        a[2] = (hi ? a[6] : a[2]) + s2;
        a[3] = (hi ? a[7] : a[3]) + s3;
    }
    {
        bool hi = (lane & 8) != 0;
        float s0 = hi ? a[0] : a[2];
        float s1 = hi ? a[1] : a[3];
        s0 = __shfl_xor_sync(FULLM, s0, 8);
        s1 = __shfl_xor_sync(FULLM, s1, 8);
        a[0] = (hi ? a[2] : a[0]) + s0;
        a[1] = (hi ? a[3] : a[1]) + s1;
    }
    {
        bool hi = (lane & 4) != 0;
        float s0 = hi ? a[0] : a[1];
        s0 = __shfl_xor_sync(FULLM, s0, 4);
        a[0] = (hi ? a[1] : a[0]) + s0;
    }
    float v = a[0];
    v += __shfl_xor_sync(FULLM, v, 2);
    v += __shfl_xor_sync(FULLM, v, 1);
    return v;
}

// ── Phase 1: streaming GEMV partials.
//   512 threads; thread owns 8 k: float4 at k=4*tid and k=2048+4*tid.
//   8-deep per-thread cp.async pipeline into private smem slots (no block
//   sync needed — each thread reads only bytes it copied). 16 warps →
//   ~240 MIO instr/row/SM (the R4/R5 binding resource, halved).
__global__ void __launch_bounds__(512, 1)
router_p1(const float* __restrict__ x, const float* __restrict__ W, int T) {
    extern __shared__ char smem[];   // STAGES * 16KB = 128KB

    const int tid  = threadIdx.x;
    const int lane = tid & 31;
    const int warp = tid >> 5;
    const int nb   = gridDim.x;

    // W regs: 8 experts x 2 chunks x 16B = 64 regs
    u64 wa0[EXP], wa1[EXP], wb0[EXP], wb1[EXP];
#pragma unroll
    for (int e = 0; e < EXP; e++) {
        ulonglong2 ta = *reinterpret_cast<const ulonglong2*>(W + e * H + tid * 4);
        ulonglong2 tb = *reinterpret_cast<const ulonglong2*>(W + e * H + 2048 + tid * 4);
        wa0[e] = ta.x; wa1[e] = ta.y;
        wb0[e] = tb.x; wb1[e] = tb.y;
    }

    unsigned sbase;
    asm("{ .reg .u64 t; cvta.to.shared.u64 t, %1; cvt.u32.u64 %0, t; }"
        : "=r"(sbase) : "l"(smem));
    const unsigned myA = sbase + tid * 16;          // chunk A slot (bytes [0,8K))
    const unsigned myB = myA + 8192;                // chunk B slot (bytes [8K,16K))

    const char* xg = reinterpret_cast<const char*>(x);
    const size_t offA = (size_t)tid * 16;
    const size_t offB = offA + 8192;

    const int r0 = blockIdx.x;

    // prologue: fill STAGES groups
#pragma unroll
    for (int s = 0; s < STAGES; s++) {
        int r = r0 + s * nb;
        if (r < T) {
            cp16(myA + s * ROWB, xg + (size_t)r * ROWB + offA);
            cp16(myB + s * ROWB, xg + (size_t)r * ROWB + offB);
        }
        cp_commit();
    }

    int s = 0;
    for (int r = r0; r < T; r += nb) {
        cp_waitN();
        __syncwarp();

        u64 ax0, ax1, bx0, bx1;
        lds128(ax0, ax1, myA + s * ROWB);
        lds128(bx0, bx1, myB + s * ROWB);

        float a8[EXP];
#pragma unroll
        for (int e = 0; e < EXP; e++) {
            u64 acc = mul2(ax0, wa0[e]);
            acc = fma2(ax1, wa1[e], acc);
            acc = fma2(bx0, wb0[e], acc);
            acc = fma2(bx1, wb1[e], acc);
            a8[e] = hadd2(acc);
        }

        float v = reduce8(a8);
        if ((lane & 3) == 0)
            g_scratch[((size_t)r * 16 + warp) * EXP + (lane >> 2)] = v;

        int rp = r + STAGES * nb;
        if (rp < T) {
            cp16(myA + s * ROWB, xg + (size_t)rp * ROWB + offA);
            cp16(myB + s * ROWB, xg + (size_t)rp * ROWB + offB);
        }
        cp_commit();

        s = (s == STAGES - 1) ? 0 : s + 1;
    }
}

// ── Phase 2: one warp per row. Lanes 0..15 each load one 8-float slot;
//   butterfly reduce, shfl softmax, broadcast scores, flat top-2.
__global__ void __launch_bounds__(256)
router_p2(int T, float* __restrict__ out, int flags) {
    const int lane = threadIdx.x & 31;
    const int r    = (blockIdx.x * 256 + threadIdx.x) >> 5;
    if (r >= T) return;

    float a[EXP] = {0.f, 0.f, 0.f, 0.f, 0.f, 0.f, 0.f, 0.f};
    if (lane < 16) {
        const float4* p = reinterpret_cast<const float4*>(g_scratch + ((size_t)r * 16 + lane) * EXP);
        float4 u = p[0], v = p[1];
        a[0] = u.x; a[1] = u.y; a[2] = u.z; a[3] = u.w;
        a[4] = v.x; a[5] = v.y; a[6] = v.z; a[7] = v.w;
    }

    float t = reduce8(a);  // lane 4e -> logit[e]

    // softmax over the 8 distributed logits (orbit of lane bits {16,8,4})
    float m = t;
    m = fmaxf(m, __shfl_xor_sync(FULLM, m, 16));
    m = fmaxf(m, __shfl_xor_sync(FULLM, m, 8));
    m = fmaxf(m, __shfl_xor_sync(FULLM, m, 4));
    float pz = __expf(t - m);
    float sden = pz;
    sden += __shfl_xor_sync(FULLM, sden, 16);
    sden += __shfl_xor_sync(FULLM, sden, 8);
    sden += __shfl_xor_sync(FULLM, sden, 4);
    float sc = __fdividef(pz, sden);

    // broadcast all 8 scores to every lane (lane 4e holds expert e)
    float se[EXP];
#pragma unroll
    for (int j = 0; j < EXP; j++)
        se[j] = __shfl_sync(FULLM, sc, ((j & 4) << 2) | ((j & 2) << 2) | ((j & 1) << 2));

    // scores: two 16B stores
    if (lane < 2) {
        float4 o = lane ? make_float4(se[4], se[5], se[6], se[7])
                        : make_float4(se[0], se[1], se[2], se[3]);
        reinterpret_cast<float4*>(out + (size_t)r * EXP)[lane] = o;
    }

    // flat top-2 (ties -> lower index, matching lax.top_k)
    float v1 = se[0]; int i1 = 0;
#pragma unroll
    for (int j = 1; j < EXP; j++)
        if (se[j] > v1) { v1 = se[j]; i1 = j; }
    float v2 = -1.0f; int i2 = 0;
#pragma unroll
    for (int j = 0; j < EXP; j++)
        if (j != i1 && se[j] > v2) { v2 = se[j]; i2 = j; }

    if (lane == 0) {
        float* outW = out + (size_t)T * EXP;
        float* outI = out + (size_t)T * (EXP + 2);
        if (flags & 1) {
            outW[(size_t)r * 2 + 0] = v1;
            outW[(size_t)r * 2 + 1] = v2;
        }
        if (flags & 2) {
            outI[(size_t)r * 2 + 0] = (float)i1;
            outI[(size_t)r * 2 + 1] = (float)i2;
        }
    }
}

extern "C" void kernel_launch(void* const* d_in, const int* in_sizes, int n_in,
                              void* d_out, int out_size) {
    const float* x = (const float*)d_in[0];
    const float* W = (const float*)d_in[1];

    int T = in_sizes[0] / H;  // 16384

    int dev = 0;
    cudaGetDevice(&dev);
    int sm = 148;
    cudaDeviceGetAttribute(&sm, cudaDevAttrMultiProcessorCount, dev);

    int flags = 0;
    if (out_size >= T * (EXP + 2)) flags |= 1;
    if (out_size >= T * (EXP + 4)) flags |= 2;

    static int smemSet = 0;
    if (!smemSet) {
        cudaFuncSetAttribute(router_p1, cudaFuncAttributeMaxDynamicSharedMemorySize,
                             STAGES * ROWB);
        smemSet = 1;
    }

    router_p1<<<sm, 512, STAGES * ROWB>>>(x, W, T);
    int blocks2 = (T * 32 + 255) / 256;   // one warp per row
    router_p2<<<blocks2, 256>>>(T, (float*)d_out, flags);
}